// round 4
// baseline (speedup 1.0000x reference)
#include <cuda_runtime.h>
#include <cuda_bf16.h>
#include <cstddef>

#define NN 100000
#define NE 1600000
#define D1 512      // hidden dim (layer1 out)
#define D2 128      // output dim
#define K1 1024     // input dim

// ---------------- scratch (static device globals; no runtime allocation) ---
// NOTE: these are referenced ONLY from device code. Passing a __device__
// symbol as a kernel argument from host code yields the host-shadow address
// (silently "works" via ATS on GB300 but reads/writes host memory) — that was
// the Round-3 bug.
__device__ float4 g_xw1[(size_t)NN * D1 / 4];   // x @ W1, later reused as out1
__device__ float4 g_agg1[(size_t)NN * D1 / 4];  // layer1 aggregation accumulator
__device__ float4 g_xw2[(size_t)NN * D2 / 4];   // out1 @ W2
__device__ float  g_deg[NN];
__device__ float  g_dinv[NN];
__device__ float  g_norm[NE];                   // per-edge norm / e2 score
__device__ float  g_ssrc[NN];
__device__ float  g_sdst[NN];
__device__ int    g_row[NE];
__device__ int    g_col[NE];
__device__ int    g_is64;

// ---------------- edge_index dtype detect + convert ------------------------
__global__ void k_detect(const int* __restrict__ ei32) {
    if (blockIdx.x != 0 || threadIdx.x != 0) return;
    int is64 = 1;
    for (int i = 1; i < 512; i += 2) {
        if (ei32[i] != 0) { is64 = 0; break; }
    }
    g_is64 = is64;
}

__global__ void k_convert(const void* __restrict__ ei) {
    int e = blockIdx.x * blockDim.x + threadIdx.x;
    if (e >= NE) return;
    if (g_is64) {
        const long long* p = (const long long*)ei;
        g_row[e] = (int)p[e];
        g_col[e] = (int)p[NE + e];
    } else {
        const int* p = (const int*)ei;
        g_row[e] = p[e];
        g_col[e] = p[NE + e];
    }
}

// ---------------- small elementwise kernels --------------------------------
__global__ void k_deg_init() {
    int i = blockIdx.x * blockDim.x + threadIdx.x;
    if (i < NN) g_deg[i] = 1.0f;   // self-loop weight
}

__global__ void k_deg_edges(const float* __restrict__ ew) {
    int e = blockIdx.x * blockDim.x + threadIdx.x;
    if (e < NE) atomicAdd(&g_deg[g_col[e]], ew[e]);
}

__global__ void k_dinv() {
    int i = blockIdx.x * blockDim.x + threadIdx.x;
    if (i < NN) g_dinv[i] = rsqrtf(g_deg[i]);   // deg >= 1 always (self loop)
}

__global__ void k_norm1(const float* __restrict__ ew) {
    int e = blockIdx.x * blockDim.x + threadIdx.x;
    if (e < NE) g_norm[e] = g_dinv[g_row[e]] * ew[e] * g_dinv[g_col[e]];
}

// e2 = relu(s_src[row] + s_dst[col] + bm); store into g_norm; accumulate deg2
__global__ void k_e2(const float* __restrict__ bm) {
    int e = blockIdx.x * blockDim.x + threadIdx.x;
    if (e < NE) {
        float s = fmaxf(g_ssrc[g_row[e]] + g_sdst[g_col[e]] + bm[0], 0.0f);
        g_norm[e] = s;
        atomicAdd(&g_deg[g_col[e]], s);
    }
}

__global__ void k_norm2() {
    int e = blockIdx.x * blockDim.x + threadIdx.x;
    if (e < NE) g_norm[e] = g_dinv[g_row[e]] * g_norm[e] * g_dinv[g_col[e]];
}

// agg1 = xw1 * dinv^2  (self-loop contribution)
__global__ void k_self1() {
    size_t idx = (size_t)blockIdx.x * blockDim.x + threadIdx.x;
    const size_t total = (size_t)NN * (D1 / 4);
    if (idx >= total) return;
    int i = (int)(idx >> 7);           // / (D1/4 = 128)
    float s = g_dinv[i]; s *= s;
    float4 v = g_xw1[idx];
    g_agg1[idx] = make_float4(v.x * s, v.y * s, v.z * s, v.w * s);
}

// out = xw2 * dinv^2 + b2  (self loop + bias)
__global__ void k_self2(const float* __restrict__ b2, float4* __restrict__ out) {
    size_t idx = (size_t)blockIdx.x * blockDim.x + threadIdx.x;
    const size_t total = (size_t)NN * (D2 / 4);
    if (idx >= total) return;
    int i = (int)(idx >> 5);           // / (D2/4 = 32)
    int j = (int)(idx & 31);
    float s = g_dinv[i]; s *= s;
    float4 v = g_xw2[idx];
    float4 bb = ((const float4*)b2)[j];
    out[idx] = make_float4(fmaf(v.x, s, bb.x), fmaf(v.y, s, bb.y),
                           fmaf(v.z, s, bb.z), fmaf(v.w, s, bb.w));
}

// ---------------- warp-per-edge scatter: dst[col] += src[row] * norm -------
// LAYER 1: src = g_xw1 (pre-relu xw), dst = g_agg1, Dv = 128 float4s
// LAYER 2: src = g_xw2,               dst = out,    Dv = 32 float4s
template <int LAYER>
__global__ void k_edge_scatter(float4* __restrict__ outp) {
    const int Dv = (LAYER == 1) ? (D1 / 4) : (D2 / 4);
    const float4* __restrict__ src = (LAYER == 1) ? g_xw1 : g_xw2;
    float4* __restrict__ dst = (LAYER == 1) ? g_agg1 : outp;

    int gw = (blockIdx.x * blockDim.x + threadIdx.x) >> 5;
    int lane = threadIdx.x & 31;
    if (gw >= NE) return;
    int r = 0, c = 0; float w = 0.0f;
    if (lane == 0) {
        r = g_row[gw];
        c = g_col[gw];
        w = g_norm[gw];
    }
    r = __shfl_sync(0xffffffffu, r, 0);
    c = __shfl_sync(0xffffffffu, c, 0);
    w = __shfl_sync(0xffffffffu, w, 0);
    const float4* s = src + (size_t)r * Dv;
    float4* d = dst + (size_t)c * Dv;
    #pragma unroll 4
    for (int j = lane; j < Dv; j += 32) {
        float4 v = s[j];
        float4 a = make_float4(v.x * w, v.y * w, v.z * w, v.w * w);
        atomicAdd(d + j, a);   // sm_90+ vector atomic
    }
}

// ---------------- relu(agg1 + b1) -> out1 (stored in g_xw1) + similarity ----
__global__ void k_relu_sim(const float* __restrict__ b1, const float* __restrict__ Wm) {
    int i = blockIdx.x;
    int t = threadIdx.x;   // 0..127, one float4 each
    size_t base = (size_t)i * (D1 / 4);
    float4 v = g_agg1[base + t];
    float4 bb = ((const float4*)b1)[t];
    float4 r;
    r.x = fmaxf(v.x + bb.x, 0.0f);
    r.y = fmaxf(v.y + bb.y, 0.0f);
    r.z = fmaxf(v.z + bb.z, 0.0f);
    r.w = fmaxf(v.w + bb.w, 0.0f);
    g_xw1[base + t] = r;   // overwrite xw1 with out1 (xw1 fully consumed)

    float4 ws = ((const float4*)Wm)[t];
    float4 wd = ((const float4*)Wm)[t + 128];
    float ps = r.x * ws.x + r.y * ws.y + r.z * ws.z + r.w * ws.w;
    float pd = r.x * wd.x + r.y * wd.y + r.z * wd.z + r.w * wd.w;
    #pragma unroll
    for (int o = 16; o > 0; o >>= 1) {
        ps += __shfl_down_sync(0xffffffffu, ps, o);
        pd += __shfl_down_sync(0xffffffffu, pd, o);
    }
    __shared__ float sps[4], spd[4];
    if ((t & 31) == 0) { sps[t >> 5] = ps; spd[t >> 5] = pd; }
    __syncthreads();
    if (t == 0) {
        g_ssrc[i] = sps[0] + sps[1] + sps[2] + sps[3];
        g_sdst[i] = spd[0] + spd[1] + spd[2] + spd[3];
    }
}

// ---------------- tiled fp32 SGEMM (128x128x8 blocks, 8x8 per thread) ------
// mode 0: C = g_xw1 = Aext(node_attr) @ B(W1)
// mode 1: C = g_xw2 = g_xw1(out1)     @ B(W2)
template <int BM, int BN, int BK, int TM, int TN>
__global__ void sgemm_tpl(const float* __restrict__ Aext, const float* __restrict__ B,
                          int M, int N, int K, int mode) {
    const float* A = (mode == 0) ? Aext : (const float*)g_xw1;
    float* C = (mode == 0) ? (float*)g_xw1 : (float*)g_xw2;

    __shared__ float As[BK][BM];
    __shared__ float Bs[BK][BN];
    const int tid = threadIdx.x;                 // 256 threads
    const int bm0 = blockIdx.y * BM;
    const int bn0 = blockIdx.x * BN;

    const int tcol = tid % (BN / TN);            // 0..15
    const int trow = tid / (BN / TN);            // 0..15

    const int aRow = tid / (BK / 4);             // 0..127
    const int aCol = (tid % (BK / 4)) * 4;       // 0 or 4
    const int bRow = tid / (BN / 4);             // 0..7
    const int bCol = (tid % (BN / 4)) * 4;       // 0..124

    float acc[TM][TN] = {};
    float rM[TM], rN[TN];

    const int gARow = bm0 + aRow;
    const bool aValid = gARow < M;
    const float* Aptr = A + (size_t)gARow * K + aCol;
    const float* Bptr = B + (size_t)bRow * N + bn0 + bCol;

    for (int k0 = 0; k0 < K; k0 += BK) {
        float4 av = aValid ? *(const float4*)(Aptr + k0) : make_float4(0, 0, 0, 0);
        As[aCol + 0][aRow] = av.x;
        As[aCol + 1][aRow] = av.y;
        As[aCol + 2][aRow] = av.z;
        As[aCol + 3][aRow] = av.w;
        *(float4*)&Bs[bRow][bCol] = *(const float4*)(Bptr + (size_t)k0 * N);
        __syncthreads();
        #pragma unroll
        for (int k = 0; k < BK; k++) {
            #pragma unroll
            for (int i = 0; i < TM; i++) rM[i] = As[k][trow * TM + i];
            #pragma unroll
            for (int j = 0; j < TN; j++) rN[j] = Bs[k][tcol * TN + j];
            #pragma unroll
            for (int i = 0; i < TM; i++)
                #pragma unroll
                for (int j = 0; j < TN; j++)
                    acc[i][j] = fmaf(rM[i], rN[j], acc[i][j]);
        }
        __syncthreads();
    }
    #pragma unroll
    for (int i = 0; i < TM; i++) {
        int row = bm0 + trow * TM + i;
        if (row >= M) continue;
        float* Crow = C + (size_t)row * N + bn0 + tcol * TN;
        #pragma unroll
        for (int j = 0; j < TN; j += 4) {
            *(float4*)(Crow + j) =
                make_float4(acc[i][j], acc[i][j + 1], acc[i][j + 2], acc[i][j + 3]);
        }
    }
}

// ---------------- launch ----------------------------------------------------
extern "C" void kernel_launch(void* const* d_in, const int* in_sizes, int n_in,
                              void* d_out, int out_size) {
    const float* node_attr = (const float*)d_in[0];      // [NN, 1024]
    const float* edge_attr = (const float*)d_in[1];      // [NE]
    const void*  edge_index = d_in[2];                   // [2, NE] int32 or int64
    // d_in[3] coords, d_in[4] frame: unused
    const float* W1 = (const float*)d_in[5];             // [1024, 512]
    const float* b1 = (const float*)d_in[6];             // [512]
    const float* W2 = (const float*)d_in[7];             // [512, 128]
    const float* b2 = (const float*)d_in[8];             // [128]
    const float* Wm = (const float*)d_in[9];             // [1, 1024]
    const float* bm = (const float*)d_in[10];            // [1]
    float4* out = (float4*)d_out;                        // [NN, 128]

    const int nodeBlocks = (NN + 255) / 256;
    const int edgeBlocks = (NE + 255) / 256;

    // ---- detect edge_index dtype and convert to int32 row/col
    k_detect<<<1, 32>>>((const int*)edge_index);
    k_convert<<<edgeBlocks, 256>>>(edge_index);

    // ---- layer 1: degrees & norms
    k_deg_init<<<nodeBlocks, 256>>>();
    k_deg_edges<<<edgeBlocks, 256>>>(edge_attr);
    k_dinv<<<nodeBlocks, 256>>>();
    k_norm1<<<edgeBlocks, 256>>>(edge_attr);

    // ---- layer 1: xw1 = node_attr @ W1
    {
        dim3 grid(D1 / 128, (NN + 127) / 128);
        sgemm_tpl<128, 128, 8, 8, 8><<<grid, 256>>>(node_attr, W1, NN, D1, K1, 0);
    }

    // ---- layer 1: aggregate (self + edges)
    k_self1<<<(int)(((size_t)NN * (D1 / 4) + 255) / 256), 256>>>();
    k_edge_scatter<1><<<NE / 8, 256>>>(nullptr);

    // ---- relu + bias -> out1 (in g_xw1); similarity dot products
    k_relu_sim<<<NN, 128>>>(b1, Wm);

    // ---- layer 2: xw2 = out1 @ W2
    {
        dim3 grid(D2 / 128, (NN + 127) / 128);
        sgemm_tpl<128, 128, 8, 8, 8><<<grid, 256>>>(node_attr /*unused*/, W2, NN, D2, D1, 1);
    }

    // ---- layer 2: e2 gate, degrees, norms
    k_deg_init<<<nodeBlocks, 256>>>();
    k_e2<<<edgeBlocks, 256>>>(bm);
    k_dinv<<<nodeBlocks, 256>>>();
    k_norm2<<<edgeBlocks, 256>>>();

    // ---- layer 2: aggregate into output
    k_self2<<<(int)(((size_t)NN * (D2 / 4) + 255) / 256), 256>>>(b2, out);
    k_edge_scatter<2><<<NE / 8, 256>>>(out);

    (void)in_sizes; (void)n_in; (void)out_size;
}

// round 7
// speedup vs baseline: 1.6502x; 1.6502x over previous
#include <cuda_runtime.h>
#include <cuda_bf16.h>
#include <cstddef>
#include <cstdint>

#define NN 100000
#define NE 1600000
#define D1 512      // hidden dim (layer1 out)
#define D2 128      // output dim
#define K1 1024     // input dim

// ---------------- scratch (static device globals; referenced ONLY from device code) ---
__device__ float4 g_xw1[(size_t)NN * D1 / 4];   // x @ W1, later reused as out1
__device__ float4 g_agg1[(size_t)NN * D1 / 4];  // layer1 aggregation accumulator
__device__ float4 g_xw2[(size_t)NN * D2 / 4];   // out1 @ W2
__device__ float  g_deg[NN];
__device__ float  g_dinv[NN];
__device__ float  g_norm[NE];                   // per-edge norm / e2 score
__device__ float  g_ssrc[NN];
__device__ float  g_sdst[NN];
__device__ int    g_row[NE];
__device__ int    g_col[NE];
__device__ int    g_is64;

// bf16 hi/lo splits
__device__ __nv_bfloat16 g_ah[(size_t)NN * K1];   // node_attr hi
__device__ __nv_bfloat16 g_al[(size_t)NN * K1];   // node_attr lo
__device__ __nv_bfloat16 g_o1h[(size_t)NN * D1];  // out1 hi
__device__ __nv_bfloat16 g_o1l[(size_t)NN * D1];  // out1 lo
__device__ __nv_bfloat16 g_w1h[(size_t)K1 * D1];
__device__ __nv_bfloat16 g_w1l[(size_t)K1 * D1];
__device__ __nv_bfloat16 g_w2h[(size_t)D1 * D2];
__device__ __nv_bfloat16 g_w2l[(size_t)D1 * D2];

// ---------------- helpers ---------------------------------------------------
__device__ __forceinline__ void split4(float4 v, uint2& ph, uint2& pl) {
    __nv_bfloat16 h0 = __float2bfloat16(v.x);
    __nv_bfloat16 h1 = __float2bfloat16(v.y);
    __nv_bfloat16 h2 = __float2bfloat16(v.z);
    __nv_bfloat16 h3 = __float2bfloat16(v.w);
    __nv_bfloat16 l0 = __float2bfloat16(v.x - __bfloat162float(h0));
    __nv_bfloat16 l1 = __float2bfloat16(v.y - __bfloat162float(h1));
    __nv_bfloat16 l2 = __float2bfloat16(v.z - __bfloat162float(h2));
    __nv_bfloat16 l3 = __float2bfloat16(v.w - __bfloat162float(h3));
    ph.x = ((uint32_t)__bfloat16_as_ushort(h1) << 16) | __bfloat16_as_ushort(h0);
    ph.y = ((uint32_t)__bfloat16_as_ushort(h3) << 16) | __bfloat16_as_ushort(h2);
    pl.x = ((uint32_t)__bfloat16_as_ushort(l1) << 16) | __bfloat16_as_ushort(l0);
    pl.y = ((uint32_t)__bfloat16_as_ushort(l3) << 16) | __bfloat16_as_ushort(l2);
}

// WHICH 0: node_attr -> g_ah/g_al ; 1: W1 -> g_w1h/l ; 2: W2 -> g_w2h/l
template <int WHICH>
__global__ void k_split(const float4* __restrict__ src, int n4) {
    int idx = blockIdx.x * blockDim.x + threadIdx.x;
    if (idx >= n4) return;
    __nv_bfloat16* Dh = (WHICH == 0) ? g_ah : (WHICH == 1) ? g_w1h : g_w2h;
    __nv_bfloat16* Dl = (WHICH == 0) ? g_al : (WHICH == 1) ? g_w1l : g_w2l;
    uint2 ph, pl;
    split4(src[idx], ph, pl);
    ((uint2*)Dh)[idx] = ph;
    ((uint2*)Dl)[idx] = pl;
}

// ---------------- edge_index dtype detect + convert ------------------------
__global__ void k_detect(const int* __restrict__ ei32) {
    if (blockIdx.x != 0 || threadIdx.x != 0) return;
    int is64 = 1;
    for (int i = 1; i < 512; i += 2) {
        if (ei32[i] != 0) { is64 = 0; break; }
    }
    g_is64 = is64;
}

__global__ void k_convert(const void* __restrict__ ei) {
    int e = blockIdx.x * blockDim.x + threadIdx.x;
    if (e >= NE) return;
    if (g_is64) {
        const long long* p = (const long long*)ei;
        g_row[e] = (int)p[e];
        g_col[e] = (int)p[NE + e];
    } else {
        const int* p = (const int*)ei;
        g_row[e] = p[e];
        g_col[e] = p[NE + e];
    }
}

// ---------------- small elementwise kernels --------------------------------
__global__ void k_deg_init() {
    int i = blockIdx.x * blockDim.x + threadIdx.x;
    if (i < NN) g_deg[i] = 1.0f;
}

__global__ void k_deg_edges(const float* __restrict__ ew) {
    int e = blockIdx.x * blockDim.x + threadIdx.x;
    if (e < NE) atomicAdd(&g_deg[g_col[e]], ew[e]);
}

__global__ void k_dinv() {
    int i = blockIdx.x * blockDim.x + threadIdx.x;
    if (i < NN) g_dinv[i] = rsqrtf(g_deg[i]);
}

__global__ void k_norm1(const float* __restrict__ ew) {
    int e = blockIdx.x * blockDim.x + threadIdx.x;
    if (e < NE) g_norm[e] = g_dinv[g_row[e]] * ew[e] * g_dinv[g_col[e]];
}

__global__ void k_e2(const float* __restrict__ bm) {
    int e = blockIdx.x * blockDim.x + threadIdx.x;
    if (e < NE) {
        float s = fmaxf(g_ssrc[g_row[e]] + g_sdst[g_col[e]] + bm[0], 0.0f);
        g_norm[e] = s;
        atomicAdd(&g_deg[g_col[e]], s);
    }
}

__global__ void k_norm2() {
    int e = blockIdx.x * blockDim.x + threadIdx.x;
    if (e < NE) g_norm[e] = g_dinv[g_row[e]] * g_norm[e] * g_dinv[g_col[e]];
}

__global__ void k_self1() {
    size_t idx = (size_t)blockIdx.x * blockDim.x + threadIdx.x;
    const size_t total = (size_t)NN * (D1 / 4);
    if (idx >= total) return;
    int i = (int)(idx >> 7);
    float s = g_dinv[i]; s *= s;
    float4 v = g_xw1[idx];
    g_agg1[idx] = make_float4(v.x * s, v.y * s, v.z * s, v.w * s);
}

__global__ void k_self2(const float* __restrict__ b2, float4* __restrict__ out) {
    size_t idx = (size_t)blockIdx.x * blockDim.x + threadIdx.x;
    const size_t total = (size_t)NN * (D2 / 4);
    if (idx >= total) return;
    int i = (int)(idx >> 5);
    int j = (int)(idx & 31);
    float s = g_dinv[i]; s *= s;
    float4 v = g_xw2[idx];
    float4 bb = ((const float4*)b2)[j];
    out[idx] = make_float4(fmaf(v.x, s, bb.x), fmaf(v.y, s, bb.y),
                           fmaf(v.z, s, bb.z), fmaf(v.w, s, bb.w));
}

// ---------------- warp-per-edge scatter ------------------------------------
template <int LAYER>
__global__ void k_edge_scatter(float4* __restrict__ outp) {
    const int Dv = (LAYER == 1) ? (D1 / 4) : (D2 / 4);
    const float4* __restrict__ src = (LAYER == 1) ? g_xw1 : g_xw2;
    float4* __restrict__ dst = (LAYER == 1) ? g_agg1 : outp;

    int gw = (blockIdx.x * blockDim.x + threadIdx.x) >> 5;
    int lane = threadIdx.x & 31;
    if (gw >= NE) return;
    int r = 0, c = 0; float w = 0.0f;
    if (lane == 0) {
        r = g_row[gw];
        c = g_col[gw];
        w = g_norm[gw];
    }
    r = __shfl_sync(0xffffffffu, r, 0);
    c = __shfl_sync(0xffffffffu, c, 0);
    w = __shfl_sync(0xffffffffu, w, 0);
    const float4* s = src + (size_t)r * Dv;
    float4* d = dst + (size_t)c * Dv;
    #pragma unroll 4
    for (int j = lane; j < Dv; j += 32) {
        float4 v = s[j];
        float4 a = make_float4(v.x * w, v.y * w, v.z * w, v.w * w);
        atomicAdd(d + j, a);
    }
}

// ---------------- relu(agg1+b1) -> out1 (g_xw1) + splits + similarity ------
__global__ void k_relu_sim(const float* __restrict__ b1, const float* __restrict__ Wm) {
    int i = blockIdx.x;
    int t = threadIdx.x;   // 0..127
    size_t base = (size_t)i * (D1 / 4);
    float4 v = g_agg1[base + t];
    float4 bb = ((const float4*)b1)[t];
    float4 r;
    r.x = fmaxf(v.x + bb.x, 0.0f);
    r.y = fmaxf(v.y + bb.y, 0.0f);
    r.z = fmaxf(v.z + bb.z, 0.0f);
    r.w = fmaxf(v.w + bb.w, 0.0f);
    g_xw1[base + t] = r;

    uint2 ph, pl;
    split4(r, ph, pl);
    ((uint2*)g_o1h)[base + t] = ph;
    ((uint2*)g_o1l)[base + t] = pl;

    float4 ws = ((const float4*)Wm)[t];
    float4 wd = ((const float4*)Wm)[t + 128];
    float ps = r.x * ws.x + r.y * ws.y + r.z * ws.z + r.w * ws.w;
    float pd = r.x * wd.x + r.y * wd.y + r.z * wd.z + r.w * wd.w;
    #pragma unroll
    for (int o = 16; o > 0; o >>= 1) {
        ps += __shfl_down_sync(0xffffffffu, ps, o);
        pd += __shfl_down_sync(0xffffffffu, pd, o);
    }
    __shared__ float sps[4], spd[4];
    if ((t & 31) == 0) { sps[t >> 5] = ps; spd[t >> 5] = pd; }
    __syncthreads();
    if (t == 0) {
        g_ssrc[i] = sps[0] + sps[1] + sps[2] + sps[3];
        g_sdst[i] = spd[0] + spd[1] + spd[2] + spd[3];
    }
}

// ---------------- bf16-split tensor-core GEMM ------------------------------
// C(fp32) = Ah*Bh + Ah*Bl + Al*Bh with fp32 accumulators.
// MODE 0: A = g_ah/g_al [NN,1024], B = g_w1h/l [1024,512], C = g_xw1
// MODE 1: A = g_o1h/l  [NN, 512], B = g_w2h/l [ 512,128], C = g_xw2
#define GBM 128
#define GBN 128
#define GBK 32
#define LDA 40    // bf16 units, 80B stride -> conflict-free ldmatrix
#define LDB 136   // bf16 units, 272B stride -> conflict-free ldmatrix

__device__ __forceinline__ void ldsm_x4(uint32_t* r, const __nv_bfloat16* p) {
    uint32_t a = (uint32_t)__cvta_generic_to_shared(p);
    asm volatile("ldmatrix.sync.aligned.m8n8.x4.shared.b16 {%0,%1,%2,%3}, [%4];"
                 : "=r"(r[0]), "=r"(r[1]), "=r"(r[2]), "=r"(r[3]) : "r"(a));
}
__device__ __forceinline__ void ldsm_x2t(uint32_t* r, const __nv_bfloat16* p) {
    uint32_t a = (uint32_t)__cvta_generic_to_shared(p);
    asm volatile("ldmatrix.sync.aligned.m8n8.x2.trans.shared.b16 {%0,%1}, [%2];"
                 : "=r"(r[0]), "=r"(r[1]) : "r"(a));
}
__device__ __forceinline__ void mma_bf16(float* c, const uint32_t* a, const uint32_t* b) {
    asm volatile(
        "mma.sync.aligned.m16n8k16.row.col.f32.bf16.bf16.f32 "
        "{%0,%1,%2,%3},{%4,%5,%6,%7},{%8,%9},{%0,%1,%2,%3};"
        : "+f"(c[0]), "+f"(c[1]), "+f"(c[2]), "+f"(c[3])
        : "r"(a[0]), "r"(a[1]), "r"(a[2]), "r"(a[3]), "r"(b[0]), "r"(b[1]));
}

template <int MODE>
__global__ void __launch_bounds__(256, 1) mma_gemm() {
    constexpr int K = (MODE == 0) ? K1 : D1;
    constexpr int N = (MODE == 0) ? D1 : D2;
    const __nv_bfloat16* __restrict__ Ah = (MODE == 0) ? g_ah : g_o1h;
    const __nv_bfloat16* __restrict__ Al = (MODE == 0) ? g_al : g_o1l;
    const __nv_bfloat16* __restrict__ Bh = (MODE == 0) ? g_w1h : g_w2h;
    const __nv_bfloat16* __restrict__ Bl = (MODE == 0) ? g_w1l : g_w2l;
    float* __restrict__ C = (MODE == 0) ? (float*)g_xw1 : (float*)g_xw2;

    __shared__ __nv_bfloat16 sAh[GBM * LDA];
    __shared__ __nv_bfloat16 sAl[GBM * LDA];
    __shared__ __nv_bfloat16 sBh[GBK * LDB];
    __shared__ __nv_bfloat16 sBl[GBK * LDB];

    const int tid = threadIdx.x;
    const int lane = tid & 31;
    const int wid = tid >> 5;
    const int warp_m = wid >> 2;           // 0..1 (64 rows each)
    const int warp_n = wid & 3;            // 0..3 (32 cols each)
    const int bm0 = blockIdx.y * GBM;
    const int bn0 = blockIdx.x * GBN;

    // gmem load mapping
    const int arow = tid >> 2;             // 0..63 (two passes)
    const int acol = (tid & 3) * 8;        // 0,8,16,24
    const int brow = tid >> 4;             // 0..15 (two passes)
    const int bcol = (tid & 15) * 8;       // 0..120

    const bool av0 = (bm0 + arow) < NN;
    const bool av1 = (bm0 + 64 + arow) < NN;
    const size_t ar0 = (size_t)min(bm0 + arow, NN - 1);
    const size_t ar1 = (size_t)min(bm0 + 64 + arow, NN - 1);

    float acc[4][4][4];
    #pragma unroll
    for (int i = 0; i < 4; i++)
        #pragma unroll
        for (int j = 0; j < 4; j++)
            #pragma unroll
            for (int q = 0; q < 4; q++) acc[i][j][q] = 0.0f;

    uint4 ra[4], rb[4];
    const uint4 z4 = make_uint4(0, 0, 0, 0);

    // prefetch k0 = 0
    {
        ra[0] = av0 ? *(const uint4*)(Ah + ar0 * K + acol) : z4;
        ra[1] = av1 ? *(const uint4*)(Ah + ar1 * K + acol) : z4;
        ra[2] = av0 ? *(const uint4*)(Al + ar0 * K + acol) : z4;
        ra[3] = av1 ? *(const uint4*)(Al + ar1 * K + acol) : z4;
        rb[0] = *(const uint4*)(Bh + (size_t)brow * N + bn0 + bcol);
        rb[1] = *(const uint4*)(Bh + (size_t)(16 + brow) * N + bn0 + bcol);
        rb[2] = *(const uint4*)(Bl + (size_t)brow * N + bn0 + bcol);
        rb[3] = *(const uint4*)(Bl + (size_t)(16 + brow) * N + bn0 + bcol);
    }

    #pragma unroll 1
    for (int k0 = 0; k0 < K; k0 += GBK) {
        __syncthreads();   // previous compute done reading smem
        *(uint4*)&sAh[arow * LDA + acol] = ra[0];
        *(uint4*)&sAh[(arow + 64) * LDA + acol] = ra[1];
        *(uint4*)&sAl[arow * LDA + acol] = ra[2];
        *(uint4*)&sAl[(arow + 64) * LDA + acol] = ra[3];
        *(uint4*)&sBh[brow * LDB + bcol] = rb[0];
        *(uint4*)&sBh[(brow + 16) * LDB + bcol] = rb[1];
        *(uint4*)&sBl[brow * LDB + bcol] = rb[2];
        *(uint4*)&sBl[(brow + 16) * LDB + bcol] = rb[3];
        __syncthreads();

        const int kn = k0 + GBK;
        if (kn < K) {
            ra[0] = av0 ? *(const uint4*)(Ah + ar0 * K + kn + acol) : z4;
            ra[1] = av1 ? *(const uint4*)(Ah + ar1 * K + kn + acol) : z4;
            ra[2] = av0 ? *(const uint4*)(Al + ar0 * K + kn + acol) : z4;
            ra[3] = av1 ? *(const uint4*)(Al + ar1 * K + kn + acol) : z4;
            rb[0] = *(const uint4*)(Bh + (size_t)(kn + brow) * N + bn0 + bcol);
            rb[1] = *(const uint4*)(Bh + (size_t)(kn + 16 + brow) * N + bn0 + bcol);
            rb[2] = *(const uint4*)(Bl + (size_t)(kn + brow) * N + bn0 + bcol);
            rb[3] = *(const uint4*)(Bl + (size_t)(kn + 16 + brow) * N + bn0 + bcol);
        }

        #pragma unroll
        for (int kk = 0; kk < GBK; kk += 16) {
            uint32_t ah[4][4], al[4][4], bh[4][2], bl[4][2];
            #pragma unroll
            for (int mt = 0; mt < 4; mt++) {
                const int mrow = warp_m * 64 + mt * 16 + (lane & 15);
                const int koff = kk + ((lane >> 4) << 3);
                ldsm_x4(ah[mt], &sAh[mrow * LDA + koff]);
                ldsm_x4(al[mt], &sAl[mrow * LDA + koff]);
            }
            #pragma unroll
            for (int nt = 0; nt < 4; nt++) {
                const int krow = kk + (lane & 15);
                const int noff = warp_n * 32 + nt * 8;
                ldsm_x2t(bh[nt], &sBh[krow * LDB + noff]);
                ldsm_x2t(bl[nt], &sBl[krow * LDB + noff]);
            }
            #pragma unroll
            for (int mt = 0; mt < 4; mt++)
                #pragma unroll
                for (int nt = 0; nt < 4; nt++) {
                    mma_bf16(acc[mt][nt], ah[mt], bh[nt]);
                    mma_bf16(acc[mt][nt], ah[mt], bl[nt]);
                    mma_bf16(acc[mt][nt], al[mt], bh[nt]);
                }
        }
    }

    // epilogue
    #pragma unroll
    for (int mt = 0; mt < 4; mt++) {
        const int r0 = bm0 + warp_m * 64 + mt * 16 + (lane >> 2);
        const int r1 = r0 + 8;
        #pragma unroll
        for (int nt = 0; nt < 4; nt++) {
            const int cc = bn0 + warp_n * 32 + nt * 8 + (lane & 3) * 2;
            if (r0 < NN)
                *(float2*)&C[(size_t)r0 * N + cc] = make_float2(acc[mt][nt][0], acc[mt][nt][1]);
            if (r1 < NN)
                *(float2*)&C[(size_t)r1 * N + cc] = make_float2(acc[mt][nt][2], acc[mt][nt][3]);
        }
    }
}

// ---------------- launch ----------------------------------------------------
extern "C" void kernel_launch(void* const* d_in, const int* in_sizes, int n_in,
                              void* d_out, int out_size) {
    const float* node_attr = (const float*)d_in[0];      // [NN, 1024]
    const float* edge_attr = (const float*)d_in[1];      // [NE]
    const void*  edge_index = d_in[2];                   // [2, NE] int32 or int64
    const float* W1 = (const float*)d_in[5];             // [1024, 512]
    const float* b1 = (const float*)d_in[6];             // [512]
    const float* W2 = (const float*)d_in[7];             // [512, 128]
    const float* b2 = (const float*)d_in[8];             // [128]
    const float* Wm = (const float*)d_in[9];             // [1, 1024]
    const float* bm = (const float*)d_in[10];            // [1]
    float4* out = (float4*)d_out;                        // [NN, 128]

    const int nodeBlocks = (NN + 255) / 256;
    const int edgeBlocks = (NE + 255) / 256;

    // ---- edge_index dtype detect + convert
    k_detect<<<1, 32>>>((const int*)edge_index);
    k_convert<<<edgeBlocks, 256>>>(edge_index);

    // ---- bf16 splits of inputs/weights
    {
        int n4 = NN * (K1 / 4);
        k_split<0><<<(n4 + 255) / 256, 256>>>((const float4*)node_attr, n4);
        int w14 = (K1 * D1) / 4;
        k_split<1><<<(w14 + 255) / 256, 256>>>((const float4*)W1, w14);
        int w24 = (D1 * D2) / 4;
        k_split<2><<<(w24 + 255) / 256, 256>>>((const float4*)W2, w24);
    }

    // ---- layer 1: degrees & norms
    k_deg_init<<<nodeBlocks, 256>>>();
    k_deg_edges<<<edgeBlocks, 256>>>(edge_attr);
    k_dinv<<<nodeBlocks, 256>>>();
    k_norm1<<<edgeBlocks, 256>>>(edge_attr);

    // ---- layer 1: xw1 = node_attr @ W1 (tensor cores, bf16-split)
    {
        dim3 grid(D1 / GBN, (NN + GBM - 1) / GBM);
        mma_gemm<0><<<grid, 256>>>();
    }

    // ---- layer 1: aggregate (self + edges)
    k_self1<<<(int)(((size_t)NN * (D1 / 4) + 255) / 256), 256>>>();
    k_edge_scatter<1><<<NE / 8, 256>>>(nullptr);

    // ---- relu + bias -> out1 (+ bf16 splits) ; similarity dots
    k_relu_sim<<<NN, 128>>>(b1, Wm);

    // ---- layer 2: xw2 = out1 @ W2 (tensor cores)
    {
        dim3 grid(D2 / GBN, (NN + GBM - 1) / GBM);
        mma_gemm<1><<<grid, 256>>>();
    }

    // ---- layer 2: e2 gate, degrees, norms
    k_deg_init<<<nodeBlocks, 256>>>();
    k_e2<<<edgeBlocks, 256>>>(bm);
    k_dinv<<<nodeBlocks, 256>>>();
    k_norm2<<<edgeBlocks, 256>>>();

    // ---- layer 2: aggregate into output
    k_self2<<<(int)(((size_t)NN * (D2 / 4) + 255) / 256), 256>>>(b2, out);
    k_edge_scatter<2><<<NE / 8, 256>>>(out);

    (void)in_sizes; (void)n_in; (void)out_size;
}

// round 8
// speedup vs baseline: 2.6032x; 1.5775x over previous
#include <cuda_runtime.h>
#include <cuda_bf16.h>
#include <cstddef>
#include <cstdint>

#define NN 100000
#define NE 1600000
#define D1 512      // hidden dim (layer1 out)
#define D2 128      // output dim
#define K1 1024     // input dim
#define NB_SCAN ((NN + 255) / 256)

// ---------------- scratch (static device globals; referenced ONLY from device code) ---
__device__ float4 g_xw1[(size_t)NN * D1 / 4];   // x @ W1, later out1 (post-relu)
__device__ float4 g_agg1[(size_t)NN * D1 / 4];  // layer1 aggregation result
__device__ float4 g_xw2[(size_t)NN * D2 / 4];   // out1 @ W2
__device__ float  g_dinv[NN];
__device__ float  g_ssrc[NN];
__device__ float  g_sdst[NN];
__device__ int    g_row[NE];
__device__ int    g_col[NE];
__device__ int    g_is64;

// CSR (grouped by destination col)
__device__ int    g_cnt[NN];
__device__ int    g_ptr[NN + 1];
__device__ int    g_cur[NN];
__device__ int    g_bsum[NB_SCAN];
__device__ int    g_boff[NB_SCAN];
__device__ int    g_csr_src[NE];   // row (source node) per CSR slot
__device__ int    g_csr_eid[NE];   // original edge id per CSR slot
__device__ float  g_wcsr[NE];      // per-slot weight: dinv[src]*ew  (layer-specific)
__device__ float  g_e2[NE];        // per-slot e2 score (layer 2)

// bf16 hi/lo weight splits
__device__ __nv_bfloat16 g_w1h[(size_t)K1 * D1];
__device__ __nv_bfloat16 g_w1l[(size_t)K1 * D1];
__device__ __nv_bfloat16 g_w2h[(size_t)D1 * D2];
__device__ __nv_bfloat16 g_w2l[(size_t)D1 * D2];

// ---------------- helpers ---------------------------------------------------
__device__ __forceinline__ void split4(float4 v, uint2& ph, uint2& pl) {
    __nv_bfloat16 h0 = __float2bfloat16(v.x);
    __nv_bfloat16 h1 = __float2bfloat16(v.y);
    __nv_bfloat16 h2 = __float2bfloat16(v.z);
    __nv_bfloat16 h3 = __float2bfloat16(v.w);
    __nv_bfloat16 l0 = __float2bfloat16(v.x - __bfloat162float(h0));
    __nv_bfloat16 l1 = __float2bfloat16(v.y - __bfloat162float(h1));
    __nv_bfloat16 l2 = __float2bfloat16(v.z - __bfloat162float(h2));
    __nv_bfloat16 l3 = __float2bfloat16(v.w - __bfloat162float(h3));
    ph.x = ((uint32_t)__bfloat16_as_ushort(h1) << 16) | __bfloat16_as_ushort(h0);
    ph.y = ((uint32_t)__bfloat16_as_ushort(h3) << 16) | __bfloat16_as_ushort(h2);
    pl.x = ((uint32_t)__bfloat16_as_ushort(l1) << 16) | __bfloat16_as_ushort(l0);
    pl.y = ((uint32_t)__bfloat16_as_ushort(l3) << 16) | __bfloat16_as_ushort(l2);
}

// WHICH 1: W1 -> g_w1h/l ; 2: W2 -> g_w2h/l
template <int WHICH>
__global__ void k_split(const float4* __restrict__ src, int n4) {
    int idx = blockIdx.x * blockDim.x + threadIdx.x;
    if (idx >= n4) return;
    __nv_bfloat16* Dh = (WHICH == 1) ? g_w1h : g_w2h;
    __nv_bfloat16* Dl = (WHICH == 1) ? g_w1l : g_w2l;
    uint2 ph, pl;
    split4(src[idx], ph, pl);
    ((uint2*)Dh)[idx] = ph;
    ((uint2*)Dl)[idx] = pl;
}

// ---------------- edge_index dtype detect + convert + histogram ------------
__global__ void k_detect(const int* __restrict__ ei32) {
    if (blockIdx.x != 0 || threadIdx.x != 0) return;
    int is64 = 1;
    for (int i = 1; i < 512; i += 2) {
        if (ei32[i] != 0) { is64 = 0; break; }
    }
    g_is64 = is64;
}

__global__ void k_zero_cnt() {
    int i = blockIdx.x * blockDim.x + threadIdx.x;
    if (i < NN) g_cnt[i] = 0;
}

__global__ void k_convert(const void* __restrict__ ei) {
    int e = blockIdx.x * blockDim.x + threadIdx.x;
    if (e >= NE) return;
    int r, c;
    if (g_is64) {
        const long long* p = (const long long*)ei;
        r = (int)p[e];
        c = (int)p[NE + e];
    } else {
        const int* p = (const int*)ei;
        r = p[e];
        c = p[NE + e];
    }
    g_row[e] = r;
    g_col[e] = c;
    atomicAdd(&g_cnt[c], 1);
}

// ---------------- exclusive scan of g_cnt -> g_ptr --------------------------
__global__ void k_scan_block() {
    __shared__ int sh[256];
    int i = blockIdx.x * 256 + threadIdx.x;
    int v = (i < NN) ? g_cnt[i] : 0;
    sh[threadIdx.x] = v;
    __syncthreads();
    // Hillis-Steele inclusive scan
    #pragma unroll
    for (int o = 1; o < 256; o <<= 1) {
        int t = (threadIdx.x >= o) ? sh[threadIdx.x - o] : 0;
        __syncthreads();
        sh[threadIdx.x] += t;
        __syncthreads();
    }
    if (i < NN) g_ptr[i] = sh[threadIdx.x] - v;   // exclusive, block-local
    if (threadIdx.x == 255) g_bsum[blockIdx.x] = sh[255];
}

__global__ void k_scan_bsum() {
    if (blockIdx.x != 0 || threadIdx.x != 0) return;
    int run = 0;
    for (int b = 0; b < NB_SCAN; b++) {
        g_boff[b] = run;
        run += g_bsum[b];
    }
}

__global__ void k_scan_add() {
    int i = blockIdx.x * blockDim.x + threadIdx.x;
    if (i < NN) {
        int p = g_ptr[i] + g_boff[i >> 8];
        g_ptr[i] = p;
        g_cur[i] = p;
    }
    if (i == 0) g_ptr[NN] = NE;
}

__global__ void k_fill() {
    int e = blockIdx.x * blockDim.x + threadIdx.x;
    if (e >= NE) return;
    int c = g_col[e];
    int pos = atomicAdd(&g_cur[c], 1);
    g_csr_src[pos] = g_row[e];
    g_csr_eid[pos] = e;
}

// ---------------- per-node degree / dinv (atomic-free via CSR) --------------
// layer1: deg = 1 + sum ew
__global__ void k_deg1(const float* __restrict__ ew) {
    int i = blockIdx.x * blockDim.x + threadIdx.x;
    if (i >= NN) return;
    int s = g_ptr[i], e = g_ptr[i + 1];
    float acc = 0.0f;
    for (int j = s; j < e; j++) acc += ew[g_csr_eid[j]];
    g_dinv[i] = rsqrtf(1.0f + acc);
}

// layer2: e2 per slot (CSR order) + deg = 1 + sum e2
__global__ void k_deg2(const float* __restrict__ bm) {
    int i = blockIdx.x * blockDim.x + threadIdx.x;
    if (i >= NN) return;
    int s = g_ptr[i], e = g_ptr[i + 1];
    float sd = g_sdst[i] + bm[0];
    float acc = 0.0f;
    for (int j = s; j < e; j++) {
        float v = fmaxf(g_ssrc[g_csr_src[j]] + sd, 0.0f);
        g_e2[j] = v;
        acc += v;
    }
    g_dinv[i] = rsqrtf(1.0f + acc);
}

// per-slot weight precompute: w = dinv[src] * ew_or_e2
__global__ void k_w1pre(const float* __restrict__ ew) {
    int j = blockIdx.x * blockDim.x + threadIdx.x;
    if (j < NE) g_wcsr[j] = g_dinv[g_csr_src[j]] * ew[g_csr_eid[j]];
}
__global__ void k_w2pre() {
    int j = blockIdx.x * blockDim.x + threadIdx.x;
    if (j < NE) g_wcsr[j] = g_dinv[g_csr_src[j]] * g_e2[j];
}

// ---------------- CSR gather aggregation (no atomics) -----------------------
// layer1: warp per dst node, 4 float4 accumulators per lane (512 floats)
__global__ void k_gather1() {
    int c = (blockIdx.x * blockDim.x + threadIdx.x) >> 5;
    int lane = threadIdx.x & 31;
    if (c >= NN) return;
    int s = g_ptr[c], e = g_ptr[c + 1];
    float4 a0 = make_float4(0, 0, 0, 0), a1 = a0, a2 = a0, a3 = a0;
    for (int j = s; j < e; j++) {
        int r = g_csr_src[j];           // uniform within warp
        float w = g_wcsr[j];
        const float4* x = g_xw1 + (size_t)r * 128 + lane;
        float4 v0 = x[0], v1 = x[32], v2 = x[64], v3 = x[96];
        a0.x = fmaf(w, v0.x, a0.x); a0.y = fmaf(w, v0.y, a0.y);
        a0.z = fmaf(w, v0.z, a0.z); a0.w = fmaf(w, v0.w, a0.w);
        a1.x = fmaf(w, v1.x, a1.x); a1.y = fmaf(w, v1.y, a1.y);
        a1.z = fmaf(w, v1.z, a1.z); a1.w = fmaf(w, v1.w, a1.w);
        a2.x = fmaf(w, v2.x, a2.x); a2.y = fmaf(w, v2.y, a2.y);
        a2.z = fmaf(w, v2.z, a2.z); a2.w = fmaf(w, v2.w, a2.w);
        a3.x = fmaf(w, v3.x, a3.x); a3.y = fmaf(w, v3.y, a3.y);
        a3.z = fmaf(w, v3.z, a3.z); a3.w = fmaf(w, v3.w, a3.w);
    }
    float dc = g_dinv[c];
    float ds = dc * dc;
    const float4* xc = g_xw1 + (size_t)c * 128 + lane;
    float4* o = g_agg1 + (size_t)c * 128 + lane;
    float4 s0 = xc[0], s1 = xc[32], s2 = xc[64], s3 = xc[96];
    o[0]  = make_float4(fmaf(dc, a0.x, ds * s0.x), fmaf(dc, a0.y, ds * s0.y),
                        fmaf(dc, a0.z, ds * s0.z), fmaf(dc, a0.w, ds * s0.w));
    o[32] = make_float4(fmaf(dc, a1.x, ds * s1.x), fmaf(dc, a1.y, ds * s1.y),
                        fmaf(dc, a1.z, ds * s1.z), fmaf(dc, a1.w, ds * s1.w));
    o[64] = make_float4(fmaf(dc, a2.x, ds * s2.x), fmaf(dc, a2.y, ds * s2.y),
                        fmaf(dc, a2.z, ds * s2.z), fmaf(dc, a2.w, ds * s2.w));
    o[96] = make_float4(fmaf(dc, a3.x, ds * s3.x), fmaf(dc, a3.y, ds * s3.y),
                        fmaf(dc, a3.z, ds * s3.z), fmaf(dc, a3.w, ds * s3.w));
}

// layer2: warp per dst node, 1 float4 per lane (128 floats), + bias, -> out
__global__ void k_gather2(const float* __restrict__ b2, float4* __restrict__ out) {
    int c = (blockIdx.x * blockDim.x + threadIdx.x) >> 5;
    int lane = threadIdx.x & 31;
    if (c >= NN) return;
    int s = g_ptr[c], e = g_ptr[c + 1];
    float4 a = make_float4(0, 0, 0, 0);
    for (int j = s; j < e; j++) {
        int r = g_csr_src[j];
        float w = g_wcsr[j];
        float4 v = g_xw2[(size_t)r * 32 + lane];
        a.x = fmaf(w, v.x, a.x); a.y = fmaf(w, v.y, a.y);
        a.z = fmaf(w, v.z, a.z); a.w = fmaf(w, v.w, a.w);
    }
    float dc = g_dinv[c];
    float ds = dc * dc;
    float4 sv = g_xw2[(size_t)c * 32 + lane];
    float4 bb = ((const float4*)b2)[lane];
    out[(size_t)c * 32 + lane] = make_float4(
        fmaf(dc, a.x, fmaf(ds, sv.x, bb.x)), fmaf(dc, a.y, fmaf(ds, sv.y, bb.y)),
        fmaf(dc, a.z, fmaf(ds, sv.z, bb.z)), fmaf(dc, a.w, fmaf(ds, sv.w, bb.w)));
}

// ---------------- relu(agg1+b1) -> out1 (g_xw1) + similarity dots -----------
__global__ void k_relu_sim(const float* __restrict__ b1, const float* __restrict__ Wm) {
    int i = blockIdx.x;
    int t = threadIdx.x;   // 0..127
    size_t base = (size_t)i * (D1 / 4);
    float4 v = g_agg1[base + t];
    float4 bb = ((const float4*)b1)[t];
    float4 r;
    r.x = fmaxf(v.x + bb.x, 0.0f);
    r.y = fmaxf(v.y + bb.y, 0.0f);
    r.z = fmaxf(v.z + bb.z, 0.0f);
    r.w = fmaxf(v.w + bb.w, 0.0f);
    g_xw1[base + t] = r;   // out1 overwrites xw1

    float4 ws = ((const float4*)Wm)[t];
    float4 wd = ((const float4*)Wm)[t + 128];
    float ps = r.x * ws.x + r.y * ws.y + r.z * ws.z + r.w * ws.w;
    float pd = r.x * wd.x + r.y * wd.y + r.z * wd.z + r.w * wd.w;
    #pragma unroll
    for (int o = 16; o > 0; o >>= 1) {
        ps += __shfl_down_sync(0xffffffffu, ps, o);
        pd += __shfl_down_sync(0xffffffffu, pd, o);
    }
    __shared__ float sps[4], spd[4];
    if ((t & 31) == 0) { sps[t >> 5] = ps; spd[t >> 5] = pd; }
    __syncthreads();
    if (t == 0) {
        g_ssrc[i] = sps[0] + sps[1] + sps[2] + sps[3];
        g_sdst[i] = spd[0] + spd[1] + spd[2] + spd[3];
    }
}

// ---------------- bf16-split tensor-core GEMM (A loaded fp32, split in-kernel)
// MODE 0: A = node_attr (arg) [NN,1024], B = g_w1h/l, C = g_xw1
// MODE 1: A = g_xw1 (out1)    [NN, 512], B = g_w2h/l, C = g_xw2
#define GBM 128
#define GBN 128
#define GBK 32
#define LDA 40    // bf16 units, 80B stride -> conflict-free ldmatrix
#define LDB 136   // bf16 units, 272B stride -> conflict-free ldmatrix

__device__ __forceinline__ void ldsm_x4(uint32_t* r, const __nv_bfloat16* p) {
    uint32_t a = (uint32_t)__cvta_generic_to_shared(p);
    asm volatile("ldmatrix.sync.aligned.m8n8.x4.shared.b16 {%0,%1,%2,%3}, [%4];"
                 : "=r"(r[0]), "=r"(r[1]), "=r"(r[2]), "=r"(r[3]) : "r"(a));
}
__device__ __forceinline__ void ldsm_x2t(uint32_t* r, const __nv_bfloat16* p) {
    uint32_t a = (uint32_t)__cvta_generic_to_shared(p);
    asm volatile("ldmatrix.sync.aligned.m8n8.x2.trans.shared.b16 {%0,%1}, [%2];"
                 : "=r"(r[0]), "=r"(r[1]) : "r"(a));
}
__device__ __forceinline__ void mma_bf16(float* c, const uint32_t* a, const uint32_t* b) {
    asm volatile(
        "mma.sync.aligned.m16n8k16.row.col.f32.bf16.bf16.f32 "
        "{%0,%1,%2,%3},{%4,%5,%6,%7},{%8,%9},{%0,%1,%2,%3};"
        : "+f"(c[0]), "+f"(c[1]), "+f"(c[2]), "+f"(c[3])
        : "r"(a[0]), "r"(a[1]), "r"(a[2]), "r"(a[3]), "r"(b[0]), "r"(b[1]));
}

template <int MODE>
__global__ void __launch_bounds__(256, 1) mma_gemm(const float* __restrict__ Aarg) {
    constexpr int K = (MODE == 0) ? K1 : D1;
    constexpr int N = (MODE == 0) ? D1 : D2;
    const float* __restrict__ A = (MODE == 0) ? Aarg : (const float*)g_xw1;
    const __nv_bfloat16* __restrict__ Bh = (MODE == 0) ? g_w1h : g_w2h;
    const __nv_bfloat16* __restrict__ Bl = (MODE == 0) ? g_w1l : g_w2l;
    float* __restrict__ C = (MODE == 0) ? (float*)g_xw1 : (float*)g_xw2;

    __shared__ __nv_bfloat16 sAh[GBM * LDA];
    __shared__ __nv_bfloat16 sAl[GBM * LDA];
    __shared__ __nv_bfloat16 sBh[GBK * LDB];
    __shared__ __nv_bfloat16 sBl[GBK * LDB];

    const int tid = threadIdx.x;
    const int lane = tid & 31;
    const int wid = tid >> 5;
    const int warp_m = wid >> 2;           // 0..1 (64 rows each)
    const int warp_n = wid & 3;            // 0..3 (32 cols each)
    const int bm0 = blockIdx.y * GBM;
    const int bn0 = blockIdx.x * GBN;

    // gmem load mapping: A fp32 (8 floats per thread per row-half)
    const int arow = tid >> 2;             // 0..63 (two halves)
    const int acol = (tid & 3) * 8;        // 0,8,16,24
    const int brow = tid >> 4;             // 0..15 (two halves)
    const int bcol = (tid & 15) * 8;       // 0..120

    const bool av0 = (bm0 + arow) < NN;
    const bool av1 = (bm0 + 64 + arow) < NN;
    const size_t ar0 = (size_t)min(bm0 + arow, NN - 1);
    const size_t ar1 = (size_t)min(bm0 + 64 + arow, NN - 1);

    float acc[4][4][4];
    #pragma unroll
    for (int i = 0; i < 4; i++)
        #pragma unroll
        for (int j = 0; j < 4; j++)
            #pragma unroll
            for (int q = 0; q < 4; q++) acc[i][j][q] = 0.0f;

    float4 ra[4];            // A fp32: rowhalf0 {acol, acol+4}, rowhalf1 {acol, acol+4}
    uint4 rb[4];
    const float4 zf4 = make_float4(0, 0, 0, 0);
    const uint4 z4 = make_uint4(0, 0, 0, 0);

    // prefetch k0 = 0
    {
        ra[0] = av0 ? *(const float4*)(A + ar0 * K + acol) : zf4;
        ra[1] = av0 ? *(const float4*)(A + ar0 * K + acol + 4) : zf4;
        ra[2] = av1 ? *(const float4*)(A + ar1 * K + acol) : zf4;
        ra[3] = av1 ? *(const float4*)(A + ar1 * K + acol + 4) : zf4;
        rb[0] = *(const uint4*)(Bh + (size_t)brow * N + bn0 + bcol);
        rb[1] = *(const uint4*)(Bh + (size_t)(16 + brow) * N + bn0 + bcol);
        rb[2] = *(const uint4*)(Bl + (size_t)brow * N + bn0 + bcol);
        rb[3] = *(const uint4*)(Bl + (size_t)(16 + brow) * N + bn0 + bcol);
    }

    #pragma unroll 1
    for (int k0 = 0; k0 < K; k0 += GBK) {
        __syncthreads();
        {
            uint2 h0, l0, h1, l1;
            split4(ra[0], h0, l0);
            split4(ra[1], h1, l1);
            *(uint4*)&sAh[arow * LDA + acol] = make_uint4(h0.x, h0.y, h1.x, h1.y);
            *(uint4*)&sAl[arow * LDA + acol] = make_uint4(l0.x, l0.y, l1.x, l1.y);
            split4(ra[2], h0, l0);
            split4(ra[3], h1, l1);
            *(uint4*)&sAh[(arow + 64) * LDA + acol] = make_uint4(h0.x, h0.y, h1.x, h1.y);
            *(uint4*)&sAl[(arow + 64) * LDA + acol] = make_uint4(l0.x, l0.y, l1.x, l1.y);
        }
        *(uint4*)&sBh[brow * LDB + bcol] = rb[0];
        *(uint4*)&sBh[(brow + 16) * LDB + bcol] = rb[1];
        *(uint4*)&sBl[brow * LDB + bcol] = rb[2];
        *(uint4*)&sBl[(brow + 16) * LDB + bcol] = rb[3];
        __syncthreads();

        const int kn = k0 + GBK;
        if (kn < K) {
            ra[0] = av0 ? *(const float4*)(A + ar0 * K + kn + acol) : zf4;
            ra[1] = av0 ? *(const float4*)(A + ar0 * K + kn + acol + 4) : zf4;
            ra[2] = av1 ? *(const float4*)(A + ar1 * K + kn + acol) : zf4;
            ra[3] = av1 ? *(const float4*)(A + ar1 * K + kn + acol + 4) : zf4;
            rb[0] = *(const uint4*)(Bh + (size_t)(kn + brow) * N + bn0 + bcol);
            rb[1] = *(const uint4*)(Bh + (size_t)(kn + 16 + brow) * N + bn0 + bcol);
            rb[2] = *(const uint4*)(Bl + (size_t)(kn + brow) * N + bn0 + bcol);
            rb[3] = *(const uint4*)(Bl + (size_t)(kn + 16 + brow) * N + bn0 + bcol);
        }

        #pragma unroll
        for (int kk = 0; kk < GBK; kk += 16) {
            uint32_t ah[4][4], al[4][4], bh[4][2], bl[4][2];
            #pragma unroll
            for (int mt = 0; mt < 4; mt++) {
                const int mrow = warp_m * 64 + mt * 16 + (lane & 15);
                const int koff = kk + ((lane >> 4) << 3);
                ldsm_x4(ah[mt], &sAh[mrow * LDA + koff]);
                ldsm_x4(al[mt], &sAl[mrow * LDA + koff]);
            }
            #pragma unroll
            for (int nt = 0; nt < 4; nt++) {
                const int krow = kk + (lane & 15);
                const int noff = warp_n * 32 + nt * 8;
                ldsm_x2t(bh[nt], &sBh[krow * LDB + noff]);
                ldsm_x2t(bl[nt], &sBl[krow * LDB + noff]);
            }
            #pragma unroll
            for (int mt = 0; mt < 4; mt++)
                #pragma unroll
                for (int nt = 0; nt < 4; nt++) {
                    mma_bf16(acc[mt][nt], ah[mt], bh[nt]);
                    mma_bf16(acc[mt][nt], ah[mt], bl[nt]);
                    mma_bf16(acc[mt][nt], al[mt], bh[nt]);
                }
        }
    }

    // epilogue
    #pragma unroll
    for (int mt = 0; mt < 4; mt++) {
        const int r0 = bm0 + warp_m * 64 + mt * 16 + (lane >> 2);
        const int r1 = r0 + 8;
        #pragma unroll
        for (int nt = 0; nt < 4; nt++) {
            const int cc = bn0 + warp_n * 32 + nt * 8 + (lane & 3) * 2;
            if (r0 < NN)
                *(float2*)&C[(size_t)r0 * N + cc] = make_float2(acc[mt][nt][0], acc[mt][nt][1]);
            if (r1 < NN)
                *(float2*)&C[(size_t)r1 * N + cc] = make_float2(acc[mt][nt][2], acc[mt][nt][3]);
        }
    }
}

// ---------------- launch ----------------------------------------------------
extern "C" void kernel_launch(void* const* d_in, const int* in_sizes, int n_in,
                              void* d_out, int out_size) {
    const float* node_attr = (const float*)d_in[0];      // [NN, 1024]
    const float* edge_attr = (const float*)d_in[1];      // [NE]
    const void*  edge_index = d_in[2];                   // [2, NE] int32 or int64
    const float* W1 = (const float*)d_in[5];             // [1024, 512]
    const float* b1 = (const float*)d_in[6];             // [512]
    const float* W2 = (const float*)d_in[7];             // [512, 128]
    const float* b2 = (const float*)d_in[8];             // [128]
    const float* Wm = (const float*)d_in[9];             // [1, 1024]
    const float* bm = (const float*)d_in[10];            // [1]
    float4* out = (float4*)d_out;                        // [NN, 128]

    const int nodeBlocks = (NN + 255) / 256;
    const int edgeBlocks = (NE + 255) / 256;
    const int warpNodeBlocks = (NN * 32 + 255) / 256;    // warp per node

    // ---- edge_index convert + CSR build
    k_detect<<<1, 32>>>((const int*)edge_index);
    k_zero_cnt<<<nodeBlocks, 256>>>();
    k_convert<<<edgeBlocks, 256>>>(edge_index);
    k_scan_block<<<NB_SCAN, 256>>>();
    k_scan_bsum<<<1, 32>>>();
    k_scan_add<<<nodeBlocks, 256>>>();
    k_fill<<<edgeBlocks, 256>>>();

    // ---- weight splits (small)
    k_split<1><<<((K1 * D1 / 4) + 255) / 256, 256>>>((const float4*)W1, K1 * D1 / 4);
    k_split<2><<<((D1 * D2 / 4) + 255) / 256, 256>>>((const float4*)W2, D1 * D2 / 4);

    // ---- layer 1: deg/dinv + per-slot weights (atomic-free)
    k_deg1<<<nodeBlocks, 256>>>(edge_attr);
    k_w1pre<<<edgeBlocks, 256>>>(edge_attr);

    // ---- layer 1: xw1 = node_attr @ W1 (tensor cores, in-kernel A split)
    {
        dim3 grid(D1 / GBN, (NN + GBM - 1) / GBM);
        mma_gemm<0><<<grid, 256>>>(node_attr);
    }

    // ---- layer 1: CSR gather (edges + self, fused)
    k_gather1<<<warpNodeBlocks, 256>>>();

    // ---- relu + bias -> out1 ; similarity dots
    k_relu_sim<<<NN, 128>>>(b1, Wm);

    // ---- layer 2: e2 + deg/dinv + weights
    k_deg2<<<nodeBlocks, 256>>>(bm);
    k_w2pre<<<edgeBlocks, 256>>>();

    // ---- layer 2: xw2 = out1 @ W2
    {
        dim3 grid(D2 / GBN, (NN + GBM - 1) / GBM);
        mma_gemm<1><<<grid, 256>>>(nullptr);
    }

    // ---- layer 2: CSR gather into output (+ bias, self fused)
    k_gather2<<<warpNodeBlocks, 256>>>(b2, out);

    (void)in_sizes; (void)n_in; (void)out_size;
}